// round 1
// baseline (speedup 1.0000x reference)
#include <cuda_runtime.h>
#include <cstdint>

namespace {

constexpr int H = 1024, W = 1024, FRAMES = 32;
constexpr int FT = 4;              // frames per block (grid.z = 8)
constexpr int PX = 16;             // pixels per thread = 8 f32x2 pairs
constexpr int COLG = 4;            // column groups per block
constexpr int TILE_W = PX * COLG;  // 64
constexpr int TILE_H = 32;
constexpr int NTHREADS = TILE_H * COLG;  // 128

__device__ __forceinline__ unsigned long long pack2(float lo, float hi) {
    unsigned long long r;
    asm("mov.b64 %0, {%1, %2};" : "=l"(r) : "f"(lo), "f"(hi));
    return r;
}

__device__ __forceinline__ void fma2(unsigned long long& d,
                                     unsigned long long a,
                                     unsigned long long b) {
    // d.f32x2 += a.f32x2 * b.f32x2  (packed dual-FMA, sm_100+)
    asm("fma.rn.f32x2 %0, %1, %2, %0;" : "+l"(d) : "l"(a), "l"(b));
}

// Accumulate 5x5 taps for PX pixels x FT frames.
// Interior path: unguarded vectorized loads. Edge path: guarded scalar loads.
template <bool EDGE>
__device__ __forceinline__ void accumulate(
    const float* __restrict__ in, const unsigned long long* __restrict__ w2,
    int h, int c0, unsigned long long acc[FT][PX / 2])
{
#pragma unroll
    for (int dyi = 0; dyi < 5; ++dyi) {
        const int rr = h + dyi - 2;
        float s[PX + 8];  // covers columns [c0-4, c0+PX+4)
        if (!EDGE) {
            const float4* p = reinterpret_cast<const float4*>(in + rr * W + (c0 - 4));
#pragma unroll
            for (int v = 0; v < (PX + 8) / 4; ++v) {
                const float4 t = p[v];
                s[4 * v + 0] = t.x; s[4 * v + 1] = t.y;
                s[4 * v + 2] = t.z; s[4 * v + 3] = t.w;
            }
        } else {
            const bool rok = (rr >= 0) && (rr < H);
#pragma unroll
            for (int v = 0; v < PX + 8; ++v) {
                const int cc = c0 - 4 + v;
                s[v] = (rok && cc >= 0 && cc < W) ? in[rr * W + cc] : 0.0f;
            }
        }
        // Pair pr[i] = (in[rr, c0-2+i], in[rr, c0-1+i]); needed i = 0..PX+2
        unsigned long long pr[PX + 3];
#pragma unroll
        for (int i = 0; i < PX + 3; ++i) pr[i] = pack2(s[i + 2], s[i + 3]);

#pragma unroll
        for (int f = 0; f < FT; ++f) {
#pragma unroll
            for (int dxi = 0; dxi < 5; ++dxi) {
                // k = (dx+2)*5 + (dy+2)
                const unsigned long long wp = w2[f * 25 + dxi * 5 + dyi];
#pragma unroll
                for (int j = 0; j < PX / 2; ++j)
                    fma2(acc[f][j], pr[2 * j + dxi], wp);
            }
        }
    }
}

__global__ void __launch_bounds__(NTHREADS)
sparse_conv_kernel(const float* __restrict__ in,
                   const float* __restrict__ wts,
                   float* __restrict__ out)
{
    __shared__ unsigned long long w2[FT * 25];
    const int tid = threadIdx.x;
    const int fbase = blockIdx.z * FT;
    if (tid < FT * 25) {
        const float w = wts[(fbase + tid / 25) * 25 + (tid % 25)];
        w2[tid] = pack2(w, w);
    }
    __syncthreads();

    const int tx = tid % COLG;
    const int ty = tid / COLG;
    const int h  = blockIdx.y * TILE_H + ty;
    const int c0 = blockIdx.x * TILE_W + tx * PX;

    unsigned long long acc[FT][PX / 2];
#pragma unroll
    for (int f = 0; f < FT; ++f)
#pragma unroll
        for (int j = 0; j < PX / 2; ++j) acc[f][j] = 0ULL;

    const bool edge = (blockIdx.x == 0) | (blockIdx.x == gridDim.x - 1) |
                      (blockIdx.y == 0) | (blockIdx.y == gridDim.y - 1);
    if (edge) accumulate<true>(in, w2, h, c0, acc);
    else      accumulate<false>(in, w2, h, c0, acc);

#pragma unroll
    for (int f = 0; f < FT; ++f) {
        float* o = out + (size_t)(fbase + f) * (size_t)(H * W) + (size_t)h * W + c0;
#pragma unroll
        for (int m = 0; m < PX / 4; ++m) {
            ulonglong2 v;
            v.x = acc[f][2 * m];
            v.y = acc[f][2 * m + 1];
            *reinterpret_cast<ulonglong2*>(o + 4 * m) = v;  // STG.128, 16B aligned
        }
    }
}

}  // namespace

extern "C" void kernel_launch(void* const* d_in, const int* in_sizes, int n_in,
                              void* d_out, int out_size)
{
    const float* in  = (const float*)d_in[0];
    const float* wts = (const float*)d_in[1];
    // d_in[2] (indices) is the fixed -2..2 5x5 grid; mapping k=(dx+2)*5+(dy+2)
    // is baked into the weight indexing above.
    float* out = (float*)d_out;

    dim3 grid(W / TILE_W, H / TILE_H, FRAMES / FT);  // 16 x 32 x 8 = 4096 blocks
    sparse_conv_kernel<<<grid, NTHREADS>>>(in, wts, out);
}

// round 2
// speedup vs baseline: 1.1996x; 1.1996x over previous
#include <cuda_runtime.h>
#include <cstdint>

namespace {

constexpr int H = 1024, W = 1024, FRAMES = 32;
constexpr int TW = 128;          // tile width (pixels)
constexpr int TH = 8;            // tile height (rows) == warps per block
constexpr int FT = 8;            // frames per block -> grid.z = 4
constexpr int NT = 256;          // threads per block (8 warps x 32 lanes)
constexpr int SW = TW + 8;       // smem row width (4-float pad each side), 136
constexpr int SH = TH + 4;       // smem rows (2-row halo each side), 12

__device__ __forceinline__ unsigned long long pack2(float lo, float hi) {
    unsigned long long r;
    asm("mov.b64 %0, {%1, %2};" : "=l"(r) : "f"(lo), "f"(hi));
    return r;
}

__device__ __forceinline__ void fma2(unsigned long long& d,
                                     unsigned long long a,
                                     unsigned long long b) {
    // d.f32x2 += a.f32x2 * b.f32x2  (packed dual-FMA, sm_100+)
    asm("fma.rn.f32x2 %0, %1, %2, %0;" : "+l"(d) : "l"(a), "l"(b));
}

__global__ void __launch_bounds__(NT)
sparse_conv_kernel(const float* __restrict__ in,
                   const float* __restrict__ wts,
                   float* __restrict__ out)
{
    __shared__ float tile[SH * SW];                 // 6528 B
    __shared__ unsigned long long w2[FT * 25];      // 1600 B

    const int tid   = threadIdx.x;
    const int c0    = blockIdx.x * TW;              // tile left col
    const int h0    = blockIdx.y * TH;              // tile top row
    const int fbase = blockIdx.z * FT;

    // Broadcast-packed weights: w2[f*25 + dx*5 + dy] = {w, w}
    if (tid < FT * 25) {
        const float w = wts[(fbase + tid / 25) * 25 + (tid % 25)];
        w2[tid] = pack2(w, w);
    }

    // Cooperative, coalesced tile fill with zero-padded halo.
    // smem (r, c) <-> global (h0 - 2 + r, c0 - 4 + c)
    for (int i = tid; i < SH * SW; i += NT) {
        const int r  = i / SW;
        const int c  = i % SW;
        const int rr = h0 - 2 + r;
        const int cc = c0 - 4 + c;
        float v = 0.0f;
        if (rr >= 0 && rr < H && cc >= 0 && cc < W) v = __ldg(in + rr * W + cc);
        tile[i] = v;
    }
    __syncthreads();

    const int lane = tid & 31;
    const int wrp  = tid >> 5;      // output row within tile
    const int xo   = lane * 4;      // 4 consecutive pixels per lane

    unsigned long long acc[FT][2];
#pragma unroll
    for (int f = 0; f < FT; ++f) { acc[f][0] = 0ULL; acc[f][1] = 0ULL; }

#pragma unroll
    for (int dy = 0; dy < 5; ++dy) {
        // Input row for this tap: smem row (wrp + dy); need local cols xo+2..xo+9,
        // read aligned window xo..xo+11 as 3x LDS.128 (conflict-free).
        const float4* rp = reinterpret_cast<const float4*>(
            &tile[(wrp + dy) * SW + xo]);
        float v[12];
#pragma unroll
        for (int m = 0; m < 3; ++m) {
            const float4 t = rp[m];
            v[4 * m + 0] = t.x; v[4 * m + 1] = t.y;
            v[4 * m + 2] = t.z; v[4 * m + 3] = t.w;
        }
        // pk[i] = (v[i+2], v[i+3]); pixel-pair p with tap dx uses pk[2p + dx]
        unsigned long long pk[7];
#pragma unroll
        for (int i = 0; i < 7; ++i) pk[i] = pack2(v[i + 2], v[i + 3]);

#pragma unroll
        for (int f = 0; f < FT; ++f) {
#pragma unroll
            for (int dx = 0; dx < 5; ++dx) {
                const unsigned long long wp = w2[f * 25 + dx * 5 + dy];
                fma2(acc[f][0], pk[dx],     wp);
                fma2(acc[f][1], pk[dx + 2], wp);
            }
        }
    }

    // Coalesced STG.128: a warp writes 512B contiguous per frame-row.
    const int hgl = h0 + wrp;
    const size_t HW = (size_t)H * W;
#pragma unroll
    for (int f = 0; f < FT; ++f) {
        float* o = out + (size_t)(fbase + f) * HW + (size_t)hgl * W + (c0 + xo);
        ulonglong2 s;
        s.x = acc[f][0];
        s.y = acc[f][1];
        *reinterpret_cast<ulonglong2*>(o) = s;
    }
}

}  // namespace

extern "C" void kernel_launch(void* const* d_in, const int* in_sizes, int n_in,
                              void* d_out, int out_size)
{
    const float* in  = (const float*)d_in[0];
    const float* wts = (const float*)d_in[1];
    // d_in[2] (indices) is the fixed -2..2 grid; k = (dx+2)*5 + (dy+2) is baked
    // into the weight indexing above.
    float* out = (float*)d_out;

    dim3 grid(W / TW, H / TH, FRAMES / FT);  // 8 x 128 x 4 = 4096 blocks
    sparse_conv_kernel<<<grid, NT>>>(in, wts, out);
}

// round 3
// speedup vs baseline: 1.4438x; 1.2036x over previous
#include <cuda_runtime.h>
#include <cstdint>

namespace {

constexpr int H = 1024, W = 1024, FRAMES = 32;
constexpr int TW = 256;          // tile width (pixels): two 128-px half-tiles
constexpr int TH = 8;            // tile height (rows) == warps per block
constexpr int FT = 4;            // frames per block -> grid.z = 8
constexpr int NT = 256;          // 8 warps
constexpr int SW = TW + 8;       // smem row width (4-float pad each side) = 264
constexpr int SH = TH + 4;       // smem rows (2-row halo each side) = 12

__device__ __forceinline__ unsigned long long pack2(float lo, float hi) {
    unsigned long long r;
    asm("mov.b64 %0, {%1, %2};" : "=l"(r) : "f"(lo), "f"(hi));
    return r;
}

__device__ __forceinline__ void fma2(unsigned long long& d,
                                     unsigned long long a,
                                     unsigned long long b) {
    // d.f32x2 += a.f32x2 * b.f32x2  (packed dual-FMA, sm_100+)
    asm("fma.rn.f32x2 %0, %1, %2, %0;" : "+l"(d) : "l"(a), "l"(b));
}

__global__ void __launch_bounds__(NT)
sparse_conv_kernel(const float* __restrict__ in,
                   const float* __restrict__ wts,
                   float* __restrict__ out)
{
    __shared__ float tile[SH * SW];                 // 12672 B
    __shared__ unsigned long long w2[FT * 25];      // 800 B

    const int tid   = threadIdx.x;
    const int c0    = blockIdx.x * TW;
    const int h0    = blockIdx.y * TH;
    const int fbase = blockIdx.z * FT;

    // Broadcast-packed weights: w2[f*25 + dx*5 + dy] = {w, w}
    if (tid < FT * 25) {
        const float w = wts[(fbase + tid / 25) * 25 + (tid % 25)];
        w2[tid] = pack2(w, w);
    }

    // Cooperative, coalesced tile fill with zero-padded halo.
    // smem (r, c) <-> global (h0 - 2 + r, c0 - 4 + c)
    for (int i = tid; i < SH * SW; i += NT) {
        const int r  = i / SW;
        const int c  = i % SW;
        const int rr = h0 - 2 + r;
        const int cc = c0 - 4 + c;
        float v = 0.0f;
        if (rr >= 0 && rr < H && cc >= 0 && cc < W) v = __ldg(in + rr * W + cc);
        tile[i] = v;
    }
    __syncthreads();

    const int lane = tid & 31;
    const int wrp  = tid >> 5;       // output row within tile
    const int xo   = lane * 4;       // group 0 base; group 1 at xo + 128

    // acc[f][2g + j]: frame f, half-tile g, pixel-pair j
    unsigned long long acc[FT][4];
#pragma unroll
    for (int f = 0; f < FT; ++f)
#pragma unroll
        for (int q = 0; q < 4; ++q) acc[f][q] = 0ULL;

#pragma unroll
    for (int dy = 0; dy < 5; ++dy) {
        const float* row = &tile[(wrp + dy) * SW];

        // Two 12-float windows (3x LDS.128 each, conflict-free: one warp = one row,
        // lanes at consecutive 16B offsets).
        float v0[12], v1[12];
        {
            const float4* p0 = reinterpret_cast<const float4*>(row + xo);
            const float4* p1 = reinterpret_cast<const float4*>(row + xo + 128);
#pragma unroll
            for (int m = 0; m < 3; ++m) {
                float4 a = p0[m], b = p1[m];
                v0[4*m+0]=a.x; v0[4*m+1]=a.y; v0[4*m+2]=a.z; v0[4*m+3]=a.w;
                v1[4*m+0]=b.x; v1[4*m+1]=b.y; v1[4*m+2]=b.z; v1[4*m+3]=b.w;
            }
        }
        // pk[i] = (v[i+2], v[i+3]); pair j with tap dx uses pk[2j + dx]
        unsigned long long pk0[7], pk1[7];
#pragma unroll
        for (int i = 0; i < 7; ++i) {
            pk0[i] = pack2(v0[i + 2], v0[i + 3]);
            pk1[i] = pack2(v1[i + 2], v1[i + 3]);
        }

#pragma unroll
        for (int f = 0; f < FT; ++f) {
#pragma unroll
            for (int dx = 0; dx < 5; ++dx) {
                const unsigned long long wp = w2[f * 25 + dx * 5 + dy];
                fma2(acc[f][0], pk0[dx],     wp);
                fma2(acc[f][1], pk0[dx + 2], wp);
                fma2(acc[f][2], pk1[dx],     wp);
                fma2(acc[f][3], pk1[dx + 2], wp);
            }
        }
    }

    // Coalesced STG.128: per frame, two fully-coalesced 512B warp stores.
    const int hgl = h0 + wrp;
    const size_t HW = (size_t)H * W;
#pragma unroll
    for (int f = 0; f < FT; ++f) {
        float* o = out + (size_t)(fbase + f) * HW + (size_t)hgl * W + c0;
        ulonglong2 s0, s1;
        s0.x = acc[f][0]; s0.y = acc[f][1];
        s1.x = acc[f][2]; s1.y = acc[f][3];
        *reinterpret_cast<ulonglong2*>(o + xo)       = s0;
        *reinterpret_cast<ulonglong2*>(o + xo + 128) = s1;
    }
}

}  // namespace

extern "C" void kernel_launch(void* const* d_in, const int* in_sizes, int n_in,
                              void* d_out, int out_size)
{
    const float* in  = (const float*)d_in[0];
    const float* wts = (const float*)d_in[1];
    // d_in[2] (indices) is the fixed -2..2 grid; k = (dx+2)*5 + (dy+2) baked in.
    float* out = (float*)d_out;

    dim3 grid(W / TW, H / TH, FRAMES / FT);  // 4 x 128 x 8 = 4096 blocks
    sparse_conv_kernel<<<grid, NT>>>(in, wts, out);
}

// round 4
// speedup vs baseline: 1.9262x; 1.3341x over previous
#include <cuda_runtime.h>
#include <cstdint>

namespace {

constexpr int H = 1024, W = 1024, FRAMES = 32;
constexpr int TW = 128;          // tile width (pixels)
constexpr int TH = 8;            // tile height == warps per block
constexpr int FT = 4;            // frames per block -> grid.z = 8
constexpr int NT = 256;          // 8 warps
constexpr int SW = TW + 8;       // smem row width (4-float pad each side) = 136
constexpr int SH = TH + 4;       // smem rows (2-row halo each side) = 12

__device__ __forceinline__ unsigned long long pack2(float lo, float hi) {
    unsigned long long r;
    asm("mov.b64 %0, {%1, %2};" : "=l"(r) : "f"(lo), "f"(hi));
    return r;
}

__device__ __forceinline__ void fma2(unsigned long long& d,
                                     unsigned long long a,
                                     unsigned long long b) {
    // d.f32x2 += a.f32x2 * b.f32x2  (packed dual-FMA, sm_100+)
    asm("fma.rn.f32x2 %0, %1, %2, %0;" : "+l"(d) : "l"(a), "l"(b));
}

__global__ void __launch_bounds__(NT, 4)
sparse_conv_kernel(const float* __restrict__ in,
                   const float* __restrict__ wts,
                   float* __restrict__ out)
{
    __shared__ float tile[SH * SW];                 // 6528 B
    __shared__ unsigned long long w2[FT * 25];      // 800 B

    const int tid   = threadIdx.x;
    const int lane  = tid & 31;
    const int wrp   = tid >> 5;
    const int c0    = blockIdx.x * TW;
    const int h0    = blockIdx.y * TH;
    const int fbase = blockIdx.z * FT;

    // Broadcast-packed weights: w2[f*25 + dx*5 + dy] = {w, w}
    if (tid < FT * 25) {
        const float w = wts[(fbase + tid / 25) * 25 + (tid % 25)];
        w2[tid] = pack2(w, w);
    }

    // Div/mod-free cooperative fill: warp w loads rows w and w+8 (if < SH).
    // smem (r, c) <-> global (h0 - 2 + r, c0 - 4 + c); zero-padded halo.
#pragma unroll
    for (int rb = 0; rb < 2; ++rb) {
        const int r = wrp + rb * 8;
        if (r < SH) {
            const int rr = h0 - 2 + r;
            const bool rok = (rr >= 0) && (rr < H);
            const float* grow = in + rr * W + (c0 - 4);
            float* srow = tile + r * SW;
#pragma unroll
            for (int c = lane; c < SW; c += 32) {
                const int cc = c0 - 4 + c;
                float v = 0.0f;
                if (rok && cc >= 0 && cc < W) v = __ldg(grow + c);
                srow[c] = v;
            }
        }
    }
    __syncthreads();

    const int xo = lane * 4;  // 4 consecutive pixels per lane

    unsigned long long acc[FT][2];
#pragma unroll
    for (int f = 0; f < FT; ++f) { acc[f][0] = 0ULL; acc[f][1] = 0ULL; }

#pragma unroll
    for (int dy = 0; dy < 5; ++dy) {
        // Smem row (wrp + dy), aligned 12-float window: 3x conflict-free LDS.128.
        const float4* rp = reinterpret_cast<const float4*>(
            &tile[(wrp + dy) * SW + xo]);
        float v[12];
#pragma unroll
        for (int m = 0; m < 3; ++m) {
            const float4 t = rp[m];
            v[4*m+0] = t.x; v[4*m+1] = t.y; v[4*m+2] = t.z; v[4*m+3] = t.w;
        }
        // pk[i] = (v[i+2], v[i+3]); pair j with tap dx uses pk[2j + dx]
        unsigned long long pk[7];
#pragma unroll
        for (int i = 0; i < 7; ++i) pk[i] = pack2(v[i + 2], v[i + 3]);

#pragma unroll
        for (int f = 0; f < FT; ++f) {
#pragma unroll
            for (int dx = 0; dx < 5; ++dx) {
                const unsigned long long wp = w2[f * 25 + dx * 5 + dy];
                fma2(acc[f][0], pk[dx],     wp);
                fma2(acc[f][1], pk[dx + 2], wp);
            }
        }
    }

    // Coalesced STG.128: a warp writes 512B contiguous per frame.
    const int hgl = h0 + wrp;
    const size_t HW = (size_t)H * W;
#pragma unroll
    for (int f = 0; f < FT; ++f) {
        float* o = out + (size_t)(fbase + f) * HW + (size_t)hgl * W + (c0 + xo);
        ulonglong2 s;
        s.x = acc[f][0];
        s.y = acc[f][1];
        *reinterpret_cast<ulonglong2*>(o) = s;
    }
}

}  // namespace

extern "C" void kernel_launch(void* const* d_in, const int* in_sizes, int n_in,
                              void* d_out, int out_size)
{
    const float* in  = (const float*)d_in[0];
    const float* wts = (const float*)d_in[1];
    // d_in[2] (indices) is the fixed -2..2 grid; k = (dx+2)*5 + (dy+2) baked in.
    float* out = (float*)d_out;

    dim3 grid(W / TW, H / TH, FRAMES / FT);  // 8 x 128 x 8 = 8192 blocks
    sparse_conv_kernel<<<grid, NT>>>(in, wts, out);
}

// round 5
// speedup vs baseline: 2.1815x; 1.1325x over previous
#include <cuda_runtime.h>
#include <cstdint>

namespace {

constexpr int H = 1024, W = 1024, FRAMES = 32;
constexpr int TW = 256;          // tile width: one warp spans it (32 lanes x 8 px)
constexpr int TH = 8;            // rows per block == warps
constexpr int FT = 4;            // frames per block -> grid.z = 8
constexpr int NT = 256;
constexpr int SW = TW + 8;       // 264 floats per smem row (4-pad each side)
constexpr int SH = TH + 4;       // 12 rows (2-row halo each side)

__device__ __forceinline__ unsigned long long pack2(float lo, float hi) {
    unsigned long long r;
    asm("mov.b64 %0, {%1, %2};" : "=l"(r) : "f"(lo), "f"(hi));
    return r;
}

__device__ __forceinline__ void fma2(unsigned long long& d,
                                     unsigned long long a,
                                     unsigned long long b) {
    // d.f32x2 += a.f32x2 * b.f32x2  (packed dual-FMA, sm_100+)
    asm("fma.rn.f32x2 %0, %1, %2, %0;" : "+l"(d) : "l"(a), "l"(b));
}

__global__ void __launch_bounds__(NT, 3)
sparse_conv_kernel(const float* __restrict__ in,
                   const float* __restrict__ wts,
                   float* __restrict__ out)
{
    __shared__ float tile[SH * SW];                   // 12672 B
    __shared__ unsigned long long wsm[5 * FT * 6];    // [dy][f][dx(5)+pad] = 960 B

    const int tid   = threadIdx.x;
    const int lane  = tid & 31;
    const int wrp   = tid >> 5;
    const int c0    = blockIdx.x * TW;
    const int h0    = blockIdx.y * TH;
    const int fbase = blockIdx.z * FT;

    // Weights re-laid-out as [dy][f][dx], each (dy,f) group padded to 6 u64 (48B).
    if (tid < FT * 25) {
        const int f  = tid / 25;
        const int k  = tid % 25;            // k = dx*5 + dy
        const int dx = k / 5;
        const int dy = k % 5;
        const float w = wts[(fbase + f) * 25 + k];
        wsm[(dy * FT + f) * 6 + dx] = pack2(w, w);
    }

    // Cooperative fill, warp-per-row (rows wrp and wrp+8), zero-padded halo.
    // smem (r, c) <-> global (h0 - 2 + r, c0 - 4 + c)
#pragma unroll
    for (int rb = 0; rb < 2; ++rb) {
        const int r = wrp + rb * 8;
        if (r < SH) {
            const int rr = h0 - 2 + r;
            const bool rok = (rr >= 0) && (rr < H);
            const float* grow = in + rr * W + (c0 - 4);
            float* srow = tile + r * SW;
#pragma unroll
            for (int c = lane; c < SW; c += 32) {
                const int cc = c0 - 4 + c;
                float v = 0.0f;
                if (rok && cc >= 0 && cc < W) v = __ldg(grow + c);
                srow[c] = v;
            }
        }
    }
    __syncthreads();

    const int xo = lane * 8;  // 8 consecutive pixels per lane

    // acc[f][j]: pixel pair j (px 2j, 2j+1)
    unsigned long long acc[FT][4];
#pragma unroll
    for (int f = 0; f < FT; ++f)
#pragma unroll
        for (int j = 0; j < 4; ++j) acc[f][j] = 0ULL;

#pragma unroll
    for (int dy = 0; dy < 5; ++dy) {
        // 16-float aligned window covering smem cols [xo, xo+15]:
        // pixels at global cols c0+xo+t need smem cols xo+2+t+dx, t=0..7, dx=0..4
        // -> cols xo+2 .. xo+13. Four conflict-free LDS.128.
        const float4* rp = reinterpret_cast<const float4*>(
            &tile[(wrp + dy) * SW + xo]);
        float v[16];
#pragma unroll
        for (int m = 0; m < 4; ++m) {
            const float4 t = rp[m];
            v[4*m+0] = t.x; v[4*m+1] = t.y; v[4*m+2] = t.z; v[4*m+3] = t.w;
        }
        // pk[i] = (v[i+2], v[i+3]); pair j, tap dx uses pk[2j + dx], i in 0..10
        unsigned long long pk[11];
#pragma unroll
        for (int i = 0; i < 11; ++i) pk[i] = pack2(v[i + 2], v[i + 3]);

#pragma unroll
        for (int f = 0; f < FT; ++f) {
            // 5 broadcast weights in 3 loads (2x LDS.128 + 1x LDS.64)
            const ulonglong2* wv = reinterpret_cast<const ulonglong2*>(
                &wsm[(dy * FT + f) * 6]);
            const ulonglong2 wa = wv[0];   // dx0, dx1
            const ulonglong2 wb = wv[1];   // dx2, dx3
            const unsigned long long w4 = wsm[(dy * FT + f) * 6 + 4];
#pragma unroll
            for (int j = 0; j < 4; ++j) {
                fma2(acc[f][j], pk[2*j + 0], wa.x);
                fma2(acc[f][j], pk[2*j + 1], wa.y);
                fma2(acc[f][j], pk[2*j + 2], wb.x);
                fma2(acc[f][j], pk[2*j + 3], wb.y);
                fma2(acc[f][j], pk[2*j + 4], w4);
            }
        }
    }

    // Stores: per frame, two STG.128 per lane; warp writes 1KB contiguous.
    const int hgl = h0 + wrp;
    const size_t HW = (size_t)H * W;
#pragma unroll
    for (int f = 0; f < FT; ++f) {
        float* o = out + (size_t)(fbase + f) * HW + (size_t)hgl * W + (c0 + xo);
        ulonglong2 s0, s1;
        s0.x = acc[f][0]; s0.y = acc[f][1];
        s1.x = acc[f][2]; s1.y = acc[f][3];
        *reinterpret_cast<ulonglong2*>(o)     = s0;
        *reinterpret_cast<ulonglong2*>(o + 4) = s1;
    }
}

}  // namespace

extern "C" void kernel_launch(void* const* d_in, const int* in_sizes, int n_in,
                              void* d_out, int out_size)
{
    const float* in  = (const float*)d_in[0];
    const float* wts = (const float*)d_in[1];
    // d_in[2] (indices) is the fixed -2..2 grid; k = (dx+2)*5 + (dy+2) baked in.
    float* out = (float*)d_out;

    dim3 grid(W / TW, H / TH, FRAMES / FT);  // 4 x 128 x 8 = 4096 blocks
    sparse_conv_kernel<<<grid, NT>>>(in, wts, out);
}